// round 17
// baseline (speedup 1.0000x reference)
#include <cuda_runtime.h>

// Entropy_70136815944310 — R17: R16 (23.0us) + accumulator fission.
// Tr split into 4 round-robin accumulators, Sr into 2 (phase-2 apply loop);
// initial-scan S/T2 split 2-way. Parallelizes the reduction spine so the 10
// applies' LDS(29)+LG2 latencies overlap instead of serializing through one
// 4-cyc FADD chain. No change to RMW ordering or arithmetic values beyond
// summation re-association (~ulp).
//
// x: [8,3,96,96] fp32 in [0,255]; out: same shape fp32.
//
// KDE kernel k(x,b) = e/(1+e)^2, e = exp(-10|x-b|), i0 = floor(x), f = x-i0.
// 4 bins i0-1..i0+2 (exact to ~1e-7; validated rel_err 3.3e-7).
// With w = 10f*log2(e), t = pn ? -w : +w, u = 2^t:
//   pn:  e_near = u (bin i0),       e_far = G2/u (bin i0+2)
//   !pn: e_near = G1*u (bin i0+1),  e_far = G1/u (bin i0-1)
// far bins use k = e(1-2e), abs err < 3e-13.
//
// Edge handling branchless: sentinel/OOB redirected to pad/guard words with
// k=0 (value-preserving RMW, race-benign; zero S/T2 contribution).
// Layout per column: [0..255] bins + [256..259] pads; 4-word guard before
// column 0 absorbs lo=-1.
//
// T2' = sum q*lg2 q;  H = ln2 * (S*lg2(S') - T2') / S',  S' = S + 1e-10.

#define IMG      96
#define SEG      8                    // output rows per thread pair
#define NSEG     (IMG / SEG)          // 12
#define THREADS  (IMG * 2)            // 192: lanes (2c, 2c+1) = column c
#define HSTRIDE  260                  // 256 bins + 4 pad
#define GUARD    4                    // words before hist: absorbs lo = -1
#define TROWS    (SEG + 4)            // 12
#define TCOLS    (IMG + 4)            // 100
#define NBINS    256
#define HIST_WORDS (GUARD + IMG * HSTRIDE)            // 24964 (mult of 4)
#define SMEM_BYTES ((HIST_WORDS + TROWS * TCOLS) * 4) // 104,656 B

#define G1    4.5399929762484854e-05f   // exp(-10)
#define G2    2.0611536224385578e-09f   // exp(-20)
#define L2E10 14.426950408889634f       // 10 * log2(e)
#define LN2   0.6931471805599453f

__device__ __forceinline__ float frcp(float v) {
    float r; asm("rcp.approx.f32 %0, %1;" : "=f"(r) : "f"(v)); return r;
}
// q * lg2(q); q==0 -> 0*lg2(1e-37)==0 exactly; tiny negative residue guarded
__device__ __forceinline__ float qlog2q(float q) {
    return q * __log2f(fmaxf(q, 1e-37f));
}

// Branchless: this thread's two bins {lo, lo+2} and masses for value v.
__device__ __forceinline__ void kde2(float v, int par,
                                     int& lo, float& klo, float& khi) {
    float fl = floorf(v);
    int   i0 = (int)fl;
    float f  = v - fl;
    bool  valid = (v >= 0.f);
    bool  pn = ((i0 & 1) == par);
    float w  = f * L2E10;
    float t  = pn ? -w : w;
    float u  = exp2f(t);                     // MUFU.EX2
    float iu = frcp(u);
    float e_near = (pn ? 1.f : G1) * u;      // bin i0 or i0+1
    float e_far  = (pn ? G2 : G1) * iu;      // bin i0+2 or i0-1
    float r  = frcp(1.f + e_near);
    float kn = e_near * r * r;
    float kf = e_far * (1.f - 2.f * e_far);
    if (!valid) i0 = pn ? 256 : 257;         // sentinel -> own pads {256,258}
    lo = pn ? i0 : i0 - 1;
    float kl = pn ? kn : kf;
    float kh = pn ? kf : kn;
    klo = (valid && lo >= 0)       ? kl : 0.f;   // lo=-1 -> guard, k=0
    khi = (valid && lo + 2 <= 255) ? kh : 0.f;   // hi=256+ -> pad, k=0
}

__global__ __launch_bounds__(THREADS, 2)
void entropy_kernel(const float* __restrict__ in, float* __restrict__ out) {
    extern __shared__ float smem[];
    float* tile = smem + HIST_WORDS;

    const int tid   = threadIdx.x;
    const int col   = tid >> 1;                    // column 0..95
    const int par   = tid & 1;                     // owns bins (b&1)==par
    const int plane = blockIdx.y;
    const int r0    = blockIdx.x * SEG;
    const float* img = in  + (size_t)plane * IMG * IMG;
    float*       o   = out + (size_t)plane * IMG * IMG;

    // ---- zero guard + all histograms + pads (float4 block-stride) ----
    {
        float4* z = (float4*)smem;
        const float4 zero = make_float4(0.f, 0.f, 0.f, 0.f);
        #pragma unroll 4
        for (int i = tid; i < HIST_WORDS / 4; i += THREADS)
            z[i] = zero;
    }

    // ---- tile: rows r0-2..r0+SEG+1, cols -2..97; OOB sentinel -10 ----
    for (int idx = tid; idx < TROWS * TCOLS; idx += THREADS) {
        int r = idx / TCOLS, c = idx % TCOLS;
        int gy = r0 + r - 2, gx = c - 2;
        float v = -10.0f;
        if ((unsigned)gy < (unsigned)IMG && (unsigned)gx < (unsigned)IMG)
            v = img[gy * IMG + gx];
        tile[idx] = v;
    }

    __syncthreads();

    float* h = smem + GUARD + col * HSTRIDE;       // 16B-aligned

    // ---- build initial histogram for y = r0 (no logs; scan follows) ----
    #pragma unroll 1
    for (int wr = 0; wr < 5; wr++) {
        const float* trow = tile + wr * TCOLS + col;
        #pragma unroll
        for (int wc = 0; wc < 5; wc++) {
            int lo; float klo, khi;
            kde2(trow[wc], par, lo, klo, khi);
            h[lo] += klo;
            h[lo + 2] += khi;
        }
    }

    // ---- initial scan: pair-partitioned interleaved float4 quads,
    //      2-way split accumulators ----
    float S0 = 0.f, S1 = 0.f, Ta = 0.f, Tb = 0.f;  // T in lg2 units
    {
        float4* h4 = (float4*)h;
        #pragma unroll 4
        for (int i = par; i < NBINS / 4; i += 2) {
            float4 q = h4[i];
            S0 += (q.x + q.y);
            S1 += (q.z + q.w);
            Ta += qlog2q(q.x) + qlog2q(q.y);
            Tb += qlog2q(q.z) + qlog2q(q.w);
        }
    }
    float S  = S0 + S1;
    float T2 = Ta + Tb;

    {
        float St = S  + __shfl_xor_sync(0xffffffffu, S,  1);
        float Tt = T2 + __shfl_xor_sync(0xffffffffu, T2, 1);
        float Sp = St + 1e-10f;
        if (par == 0)
            o[r0 * IMG + col] =
                LN2 * __fdividef(St * __log2f(Sp) - Tt, Sp);
    }

    // ---- slide down: remove tile row step-1, add tile row step+4 ----
    #pragma unroll 1
    for (int step = 1; step < SEG; step++) {
        const float* rem = tile + (step - 1) * TCOLS + col;
        const float* add = rem + 5 * TCOLS;

        // Phase 1: batch all 10 kde evals into regs (MUFUs pipeline)
        int   lo[10];
        float kl[10], kh[10];
        #pragma unroll
        for (int i = 0; i < 10; i++) {
            float v = (i < 5) ? rem[i] : add[i - 5];
            kde2(v, par, lo[i], kl[i], kh[i]);
            if (i < 5) { kl[i] = -kl[i]; kh[i] = -kh[i]; }  // folds into FADD
        }

        // Phase 2: 10 ordered RMW pairs with fissioned accumulators
        // (RMW order preserved; only the reduction spine is parallelized)
        float Tr[4] = {0.f, 0.f, 0.f, 0.f};
        float SrA = 0.f, SrB = 0.f;
        #pragma unroll
        for (int i = 0; i < 10; i++) {
            int   b  = lo[i];
            float q0 = h[b], q1 = h[b + 2];
            float n0 = q0 + kl[i], n1 = q1 + kh[i];
            h[b] = n0; h[b + 2] = n1;
            Tr[i & 3] += (qlog2q(n0) - qlog2q(q0))
                       + (qlog2q(n1) - qlog2q(q1));
            if (i & 1) SrA += kl[i] + kh[i];
            else       SrB += kl[i] + kh[i];
        }
        S  += SrA + SrB;
        T2 += (Tr[0] + Tr[1]) + (Tr[2] + Tr[3]);

        float St = S  + __shfl_xor_sync(0xffffffffu, S,  1);
        float Tt = T2 + __shfl_xor_sync(0xffffffffu, T2, 1);
        float Sp = St + 1e-10f;
        if (par == 0)
            o[(r0 + step) * IMG + col] =
                LN2 * __fdividef(St * __log2f(Sp) - Tt, Sp);
    }
}

extern "C" void kernel_launch(void* const* d_in, const int* in_sizes, int n_in,
                              void* d_out, int out_size) {
    const float* x = (const float*)d_in[0];
    float* out = (float*)d_out;

    cudaFuncSetAttribute(entropy_kernel,
                         cudaFuncAttributeMaxDynamicSharedMemorySize, SMEM_BYTES);

    int planes = in_sizes[0] / (IMG * IMG);   // 24
    dim3 grid(NSEG, planes);                  // (12, 24) = 288 CTAs
    entropy_kernel<<<grid, THREADS, SMEM_BYTES>>>(x, out);
}